// round 6
// baseline (speedup 1.0000x reference)
#include <cuda_runtime.h>
#include <cuda_bf16.h>
#include <cstdint>

constexpr int N_NODES = 50000;
constexpr int DIM     = 256;   // IN == OUT
constexpr int KSEL    = 32;

// ---------------------------------------------------------------------------
// Device-global scratch (allocation-free rule)
// ---------------------------------------------------------------------------
__device__ uint32_t g_topk[(size_t)N_NODES * KSEL]; // packed val(24b)|col(8b)
__device__ uint16_t g_ahi [(size_t)N_NODES * DIM];  // feat hi (bf16 bits)
__device__ uint16_t g_alo [(size_t)N_NODES * DIM];  // feat lo
__device__ uint16_t g_whi [2 * DIM * DIM];          // [Wself;Wneigh] hi
__device__ uint16_t g_wlo [2 * DIM * DIM];          // [Wself;Wneigh] lo

// ---------------------------------------------------------------------------
// helpers
// ---------------------------------------------------------------------------
__device__ __forceinline__ uint32_t smem_u32(const void* p) {
    uint32_t a;
    asm("{ .reg .u64 t; cvta.to.shared.u64 t, %1; cvt.u32.u64 %0, t; }"
        : "=r"(a) : "l"(p));
    return a;
}
__device__ __forceinline__ void cpa16(uint32_t dst, const void* src, bool ok) {
    asm volatile("cp.async.cg.shared.global [%0], [%1], 16, %2;"
                 :: "r"(dst), "l"(src), "r"(ok ? 16 : 0) : "memory");
}
__device__ __forceinline__ void cpa_commit() {
    asm volatile("cp.async.commit_group;" ::: "memory");
}
template <int N>
__device__ __forceinline__ void cpa_wait() {
    asm volatile("cp.async.wait_group %0;" :: "n"(N) : "memory");
}
__device__ __forceinline__ void ldsm4(uint32_t addr, uint32_t r[4]) {
    asm volatile("ldmatrix.sync.aligned.m8n8.x4.shared.b16 {%0,%1,%2,%3}, [%4];"
                 : "=r"(r[0]), "=r"(r[1]), "=r"(r[2]), "=r"(r[3]) : "r"(addr));
}
__device__ __forceinline__ void mma16816(float c[4], const uint32_t a[4],
                                         uint32_t b0, uint32_t b1) {
    asm volatile(
        "mma.sync.aligned.m16n8k16.row.col.f32.bf16.bf16.f32 "
        "{%0,%1,%2,%3},{%4,%5,%6,%7},{%8,%9},{%0,%1,%2,%3};"
        : "+f"(c[0]), "+f"(c[1]), "+f"(c[2]), "+f"(c[3])
        : "r"(a[0]), "r"(a[1]), "r"(a[2]), "r"(a[3]), "r"(b0), "r"(b1));
}

// ---------------------------------------------------------------------------
// Kernel 0: split fp32 -> bf16 hi/lo (2-wide unrolled for MLP)
// ---------------------------------------------------------------------------
__device__ __forceinline__ void split4(float4 v, uint2& hi, uint2& lo) {
    __nv_bfloat16 h0 = __float2bfloat16(v.x), h1 = __float2bfloat16(v.y);
    __nv_bfloat16 h2 = __float2bfloat16(v.z), h3 = __float2bfloat16(v.w);
    __nv_bfloat16 l0 = __float2bfloat16(v.x - __bfloat162float(h0));
    __nv_bfloat16 l1 = __float2bfloat16(v.y - __bfloat162float(h1));
    __nv_bfloat16 l2 = __float2bfloat16(v.z - __bfloat162float(h2));
    __nv_bfloat16 l3 = __float2bfloat16(v.w - __bfloat162float(h3));
    hi.x = (uint32_t)__bfloat16_as_ushort(h0) | ((uint32_t)__bfloat16_as_ushort(h1) << 16);
    hi.y = (uint32_t)__bfloat16_as_ushort(h2) | ((uint32_t)__bfloat16_as_ushort(h3) << 16);
    lo.x = (uint32_t)__bfloat16_as_ushort(l0) | ((uint32_t)__bfloat16_as_ushort(l1) << 16);
    lo.y = (uint32_t)__bfloat16_as_ushort(l2) | ((uint32_t)__bfloat16_as_ushort(l3) << 16);
}

__device__ __forceinline__ void split_task(size_t i, size_t nA4,
                                           const float* feat,
                                           const float* Wself,
                                           const float* Wneigh) {
    float4 v; uint2 *hd, *ld;
    if (i < nA4) {
        v = ((const float4*)feat)[i];
        hd = (uint2*)g_ahi + i; ld = (uint2*)g_alo + i;
    } else {
        size_t j = i - nA4;
        const float* W = (j < 16384) ? Wself : Wneigh;
        size_t jj = (j < 16384) ? j : j - 16384;
        v = ((const float4*)W)[jj];
        hd = (uint2*)g_whi + j; ld = (uint2*)g_wlo + j;
    }
    uint2 hi, lo; split4(v, hi, lo);
    *hd = hi; *ld = lo;
}

__global__ __launch_bounds__(256)
void split_kernel(const float* __restrict__ feat,
                  const float* __restrict__ Wself,
                  const float* __restrict__ Wneigh, int n)
{
    size_t nA4 = (size_t)n * DIM / 4;
    size_t nW4 = (size_t)2 * DIM * DIM / 4;   // 32768
    size_t tot = nA4 + nW4;
    size_t stride = (size_t)gridDim.x * blockDim.x;
    size_t i = (size_t)blockIdx.x * blockDim.x + threadIdx.x;
    for (; i + stride < tot; i += 2 * stride) {
        split_task(i, nA4, feat, Wself, Wneigh);
        split_task(i + stride, nA4, feat, Wself, Wneigh);
    }
    if (i < tot) split_task(i, nA4, feat, Wself, Wneigh);
}

// ---------------------------------------------------------------------------
// Kernel 1: fused HMMA GEMM + top-k.  (unchanged from round 5)
// CTA tile 128x256xK256, BK=32, 3 cp.async stages, 512 threads (16 warps).
// mat=0: h_self -> out directly.
// mat=1: feat_neigh+bias -> smem tile -> per-warp top-32 -> packed g_topk.
// GEMM: acc += Ahi*Bhi + Ahi*Blo + Alo*Bhi
// ---------------------------------------------------------------------------
constexpr int RS      = 40;                     // smem row stride (bf16)
constexpr int A_TILE  = 128 * RS * 2;           // 10240 B
constexpr int B_TILE  = 256 * RS * 2;           // 20480 B
constexpr int STAGE   = 2 * A_TILE + 2 * B_TILE;// 61440 B
constexpr int GEMM_SMEM = 3 * STAGE;            // 184320 B (>= 128*260*4 tile)
constexpr int RS2     = 260;                    // fp32 tile stride (pad 4)
constexpr float ERRB  = 1e-3f;

__device__ __forceinline__ void load_stage(uint32_t sb, int kt, int row0,
                                           int mat, int n, int tid)
{
    {   // A: 128 rows x 32 k, hi+lo
        int row = tid >> 2, kc = (tid & 3) * 8;
        uint32_t soff = (uint32_t)(row * RS + kc) * 2;
        int gr = row0 + row;
        bool ok = gr < n;
        size_t aidx = (size_t)(ok ? gr : 0) * DIM + kt * 32 + kc;
        cpa16(sb + soff,          g_ahi + aidx, ok);
        cpa16(sb + A_TILE + soff, g_alo + aidx, ok);
    }
    #pragma unroll
    for (int h = 0; h < 2; h++) {   // B: 256 rows x 32 k, hi+lo
        int t = tid + h * 512;
        int row = t >> 2, kc = (t & 3) * 8;
        uint32_t soff = (uint32_t)(row * RS + kc) * 2;
        size_t bidx = (size_t)(mat * DIM + row) * DIM + kt * 32 + kc;
        cpa16(sb + 2 * A_TILE + soff,          g_whi + bidx, true);
        cpa16(sb + 2 * A_TILE + B_TILE + soff, g_wlo + bidx, true);
    }
}

__global__ __launch_bounds__(512, 1)
void gemm_topk_kernel(const float* __restrict__ feat,
                      const float* __restrict__ Wneigh,
                      const float* __restrict__ bneigh,
                      float* __restrict__ out, int n)
{
    extern __shared__ char smem[];
    const uint32_t sbase = smem_u32(smem);
    const int tid = threadIdx.x, lane = tid & 31, wid = tid >> 5;
    const int warp_m = wid & 3, warp_n = wid >> 2;
    const int mat = blockIdx.x;
    const int row0 = blockIdx.y * 128;

    float acc[2][8][4] = {};

    load_stage(sbase,         0, row0, mat, n, tid); cpa_commit();
    load_stage(sbase + STAGE, 1, row0, mat, n, tid); cpa_commit();

    #pragma unroll 1
    for (int kt = 0; kt < 8; kt++) {
        if (kt < 7) cpa_wait<1>(); else cpa_wait<0>();
        __syncthreads();
        if (kt < 6) {
            load_stage(sbase + ((kt + 2) % 3) * STAGE, kt + 2, row0, mat, n, tid);
            cpa_commit();
        }

        const uint32_t st = sbase + (kt % 3) * STAGE;
        #pragma unroll
        for (int ks = 0; ks < 2; ks++) {
            const int k0 = ks * 16;
            uint32_t ahi[2][4], alo[2][4];
            #pragma unroll
            for (int mf = 0; mf < 2; mf++) {
                uint32_t ra = st + (uint32_t)((warp_m * 32 + mf * 16 + (lane & 15)) * RS
                                              + k0 + (lane >> 4) * 8) * 2;
                ldsm4(ra, ahi[mf]);
                ldsm4(ra + A_TILE, alo[mf]);
            }
            #pragma unroll
            for (int ng = 0; ng < 4; ng++) {
                uint32_t bhi4[4], blo4[4];
                uint32_t rb = st + 2 * A_TILE
                    + (uint32_t)((warp_n * 64 + ng * 16 + (lane >> 4) * 8 + (lane & 7)) * RS
                                 + k0 + ((lane >> 3) & 1) * 8) * 2;
                ldsm4(rb, bhi4);
                ldsm4(rb + B_TILE, blo4);
                #pragma unroll
                for (int sub = 0; sub < 2; sub++) {
                    int nf = ng * 2 + sub;
                    #pragma unroll
                    for (int mf = 0; mf < 2; mf++) {
                        mma16816(acc[mf][nf], ahi[mf], bhi4[sub * 2], bhi4[sub * 2 + 1]);
                        mma16816(acc[mf][nf], ahi[mf], blo4[sub * 2], blo4[sub * 2 + 1]);
                        mma16816(acc[mf][nf], alo[mf], bhi4[sub * 2], bhi4[sub * 2 + 1]);
                    }
                }
            }
        }
    }

    if (mat == 0) {
        // h_self straight to global
        #pragma unroll
        for (int nf = 0; nf < 8; nf++) {
            int col = warp_n * 64 + nf * 8 + (lane & 3) * 2;
            #pragma unroll
            for (int mf = 0; mf < 2; mf++) {
                int r0 = row0 + warp_m * 32 + mf * 16 + (lane >> 2);
                if (r0 < n)
                    *(float2*)(out + (size_t)r0 * DIM + col) =
                        make_float2(acc[mf][nf][0], acc[mf][nf][1]);
                int r1 = r0 + 8;
                if (r1 < n)
                    *(float2*)(out + (size_t)r1 * DIM + col) =
                        make_float2(acc[mf][nf][2], acc[mf][nf][3]);
            }
        }
        return;
    }

    // ---- mat == 1: feat_neigh + bias -> smem tile, then fused top-k ----
    __syncthreads();                      // done reading pipeline smem
    float* tile = (float*)smem;
    #pragma unroll
    for (int nf = 0; nf < 8; nf++) {
        int col = warp_n * 64 + nf * 8 + (lane & 3) * 2;
        float2 b = *(const float2*)(bneigh + col);
        #pragma unroll
        for (int mf = 0; mf < 2; mf++) {
            int r0 = warp_m * 32 + mf * 16 + (lane >> 2);
            tile[r0 * RS2 + col]     = acc[mf][nf][0] + b.x;
            tile[r0 * RS2 + col + 1] = acc[mf][nf][1] + b.y;
            int r1 = r0 + 8;
            tile[r1 * RS2 + col]     = acc[mf][nf][2] + b.x;
            tile[r1 * RS2 + col + 1] = acc[mf][nf][3] + b.y;
        }
    }
    __syncthreads();

    // each warp: 8 rows of top-32
    #pragma unroll 1
    for (int r8 = 0; r8 < 8; r8++) {
        const int lrow = wid * 8 + r8;
        const int grow = row0 + lrow;
        if (grow >= n) break;             // warp-uniform

        const float* srcr = tile + lrow * RS2;
        float v[8]; uint32_t u[8];
        #pragma unroll
        for (int i = 0; i < 8; i++) {
            v[i] = srcr[lane + i * 32];
            uint32_t s = __float_as_uint(v[i]);
            u[i] = (s & 0x80000000u) ? ~s : (s | 0x80000000u);
        }

        // radix select with early exit (count == 32 -> unique separation)
        uint32_t T = 0;
        #pragma unroll 1
        for (int bit = 31; bit >= 0; bit--) {
            uint32_t cand = T | (1u << bit);
            int c = 0;
            #pragma unroll
            for (int i = 0; i < 8; i++) c += (u[i] >= cand);
            c = __reduce_add_sync(0xffffffffu, c);
            if (c >= KSEL) { T = cand; if (c == KSEL) break; }
        }
        // v32 = approx value of the 32nd largest = min over selected
        float mn = __uint_as_float(0x7f800000);   // +inf
        #pragma unroll
        for (int i = 0; i < 8; i++)
            if (u[i] >= T) mn = fminf(mn, v[i]);
        #pragma unroll
        for (int off = 16; off; off >>= 1)
            mn = fminf(mn, __shfl_xor_sync(0xffffffffu, mn, off));
        const float v32 = mn;
        const float hi_thr = v32 + 2.f * ERRB;
        const float lo_thr = v32 - 2.f * ERRB;

        int cntS = 0, cntB = 0, bm = 0;
        #pragma unroll
        for (int i = 0; i < 8; i++) {
            bool sure = v[i] > hi_thr;
            bool bnd  = !sure && (v[i] >= lo_thr);
            cntS += sure; cntB += bnd;
            if (bnd) bm |= (1 << i);
        }
        cntS = __reduce_add_sync(0xffffffffu, cntS);
        int cntBw = __reduce_add_sync(0xffffffffu, cntB);
        const int need = KSEL - cntS;

        int picked = 0;
        float ex[8];
        const bool exact_path = (cntBw != need);
        if (exact_path) {
            // exact fp32 recompute for boundary elements (rare)
            const float* fr = feat + (size_t)grow * DIM;
            #pragma unroll 1
            for (int i = 0; i < 8; i++) {
                uint32_t bal = __ballot_sync(0xffffffffu, (bm >> i) & 1);
                while (bal) {
                    int owner = __ffs(bal) - 1; bal &= bal - 1;
                    int col = owner + i * 32;
                    const float* wr = Wneigh + (size_t)col * DIM;
                    float p = 0.f;
                    #pragma unroll
                    for (int j = 0; j < 8; j++)
                        p = fmaf(fr[lane + j * 32], wr[lane + j * 32], p);
                    #pragma unroll
                    for (int off = 16; off; off >>= 1)
                        p += __shfl_xor_sync(0xffffffffu, p, off);
                    if (lane == owner) ex[i] = p + bneigh[col];
                }
            }
            int rem = need, avail = bm;
            while (rem > 0) {
                float bv = __uint_as_float(0xff800000);   // -inf
                int bc = 0x7fffffff;
                #pragma unroll
                for (int i = 0; i < 8; i++)
                    if ((avail >> i) & 1) {
                        float e = ex[i]; int c = lane + i * 32;
                        if (e > bv || (e == bv && c < bc)) { bv = e; bc = c; }
                    }
                #pragma unroll
                for (int off = 16; off; off >>= 1) {
                    float ov = __shfl_xor_sync(0xffffffffu, bv, off);
                    int   oc = __shfl_xor_sync(0xffffffffu, bc, off);
                    if (ov > bv || (ov == bv && oc < bc)) { bv = ov; bc = oc; }
                }
                if (lane == (bc & 31)) {
                    avail  &= ~(1 << (bc >> 5));
                    picked |=  (1 << (bc >> 5));
                }
                rem--;
            }
        } else {
            picked = bm;
        }

        // packed compaction write: val(24b rounded) | col(8b)
        const uint32_t ltmask = (1u << lane) - 1u;
        int basep = 0;
        uint32_t* __restrict__ dst = g_topk + (size_t)grow * KSEL;
        #pragma unroll
        for (int i = 0; i < 8; i++) {
            bool sure = v[i] > hi_thr;
            bool pick = (picked >> i) & 1;
            bool sel = sure || pick;
            float wv = (pick && exact_path) ? ex[i] : v[i];
            uint32_t bs = __ballot_sync(0xffffffffu, sel);
            if (sel) {
                int pos = basep + __popc(bs & ltmask);
                uint32_t bits = (__float_as_uint(wv) + 0x80u) & 0xFFFFFF00u;
                dst[pos] = bits | (uint32_t)(lane + i * 32);
            }
            basep += __popc(bs);
        }
    }
}

// ---------------------------------------------------------------------------
// Kernel 2: CSR SpMM over packed sparse rows, accumulate onto h_self.
// One warp per dst row; FOUR independent smem accumulator copies per warp
// so the RMW chains of consecutive edges are provably disjoint (4x MLP).
// Within a copy, cross-edge same-column RMWs are ordered by warp program
// order (lanes lockstep; distinct cols within one edge are guaranteed).
// ---------------------------------------------------------------------------
__global__ __launch_bounds__(256)
void spmm_kernel(const int* __restrict__ indices,
                 const int* __restrict__ indptr,
                 float* __restrict__ out, int n)
{
    __shared__ float accs[8][4][DIM];    // 32 KB
    const int warp = threadIdx.x >> 5;
    const int lane = threadIdx.x & 31;
    const int row = blockIdx.x * 8 + warp;
    if (row >= n) return;

    float* a0 = accs[warp][0];
    float* a1 = accs[warp][1];
    float* a2 = accs[warp][2];
    float* a3 = accs[warp][3];
    #pragma unroll
    for (int i = 0; i < 8; i++) {
        int c = lane + i * 32;
        a0[c] = 0.f; a1[c] = 0.f; a2[c] = 0.f; a3[c] = 0.f;
    }
    __syncwarp();

    const int s = indptr[row];
    const int e = indptr[row + 1];
    int j = s;
    for (; j + 4 <= e; j += 4) {
        int i0 = indices[j], i1 = indices[j+1], i2 = indices[j+2], i3 = indices[j+3];
        uint32_t p0 = __ldg(&g_topk[(size_t)i0 * KSEL + lane]);
        uint32_t p1 = __ldg(&g_topk[(size_t)i1 * KSEL + lane]);
        uint32_t p2 = __ldg(&g_topk[(size_t)i2 * KSEL + lane]);
        uint32_t p3 = __ldg(&g_topk[(size_t)i3 * KSEL + lane]);
        a0[p0 & 0xFF] += __uint_as_float(p0 & 0xFFFFFF00u);
        a1[p1 & 0xFF] += __uint_as_float(p1 & 0xFFFFFF00u);
        a2[p2 & 0xFF] += __uint_as_float(p2 & 0xFFFFFF00u);
        a3[p3 & 0xFF] += __uint_as_float(p3 & 0xFFFFFF00u);
    }
    if (j + 2 <= e) {
        int i0 = indices[j], i1 = indices[j+1];
        uint32_t p0 = __ldg(&g_topk[(size_t)i0 * KSEL + lane]);
        uint32_t p1 = __ldg(&g_topk[(size_t)i1 * KSEL + lane]);
        a0[p0 & 0xFF] += __uint_as_float(p0 & 0xFFFFFF00u);
        a1[p1 & 0xFF] += __uint_as_float(p1 & 0xFFFFFF00u);
        j += 2;
    }
    if (j < e) {
        uint32_t p0 = __ldg(&g_topk[(size_t)indices[j] * KSEL + lane]);
        a2[p0 & 0xFF] += __uint_as_float(p0 & 0xFFFFFF00u);
    }
    __syncwarp();

    #pragma unroll
    for (int i = 0; i < 8; i++) {
        int c = lane + i * 32;
        float sum = (a0[c] + a1[c]) + (a2[c] + a3[c]);
        out[(size_t)row * DIM + c] += sum;
    }
}

// ---------------------------------------------------------------------------
extern "C" void kernel_launch(void* const* d_in, const int* in_sizes, int n_in,
                              void* d_out, int out_size)
{
    const float* feat    = (const float*)d_in[0];
    const float* Wself   = (const float*)d_in[1];
    const float* Wneigh  = (const float*)d_in[2];
    const float* bneigh  = (const float*)d_in[3];
    const int*   indices = (const int*)d_in[4];
    const int*   indptr  = (const int*)d_in[5];
    float* out = (float*)d_out;

    const int n = in_sizes[0] / DIM;   // 50000

    cudaFuncSetAttribute(gemm_topk_kernel,
                         cudaFuncAttributeMaxDynamicSharedMemorySize, GEMM_SMEM);

    // 0) fp32 -> bf16 hi/lo splits
    split_kernel<<<1024, 256>>>(feat, Wself, Wneigh, n);

    // 1) fused GEMM + top-k: h_self -> out, top-32(feat_neigh+b) -> g_topk
    dim3 ggrid(2, (n + 127) / 128);
    gemm_topk_kernel<<<ggrid, 512, GEMM_SMEM>>>(feat, Wneigh, bneigh, out, n);

    // 2) SpMM accumulate onto h_self
    int blocks_rows = (n + 7) / 8;
    spmm_kernel<<<blocks_rows, 256>>>(indices, indptr, out, n);
}

// round 7
// speedup vs baseline: 1.0516x; 1.0516x over previous
#include <cuda_runtime.h>
#include <cuda_bf16.h>
#include <cstdint>

constexpr int N_NODES = 50000;
constexpr int DIM     = 256;   // IN == OUT
constexpr int KSEL    = 32;

// ---------------------------------------------------------------------------
// Device-global scratch (allocation-free rule)
// ---------------------------------------------------------------------------
__device__ uint32_t g_topk[(size_t)N_NODES * KSEL]; // packed val(24b)|col(8b)
__device__ uint16_t g_ahi [(size_t)N_NODES * DIM];  // feat hi (bf16 bits)
__device__ uint16_t g_alo [(size_t)N_NODES * DIM];  // feat lo
__device__ uint16_t g_whi [2 * DIM * DIM];          // [Wself;Wneigh] hi
__device__ uint16_t g_wlo [2 * DIM * DIM];          // [Wself;Wneigh] lo

// ---------------------------------------------------------------------------
// helpers
// ---------------------------------------------------------------------------
__device__ __forceinline__ uint32_t smem_u32(const void* p) {
    uint32_t a;
    asm("{ .reg .u64 t; cvta.to.shared.u64 t, %1; cvt.u32.u64 %0, t; }"
        : "=r"(a) : "l"(p));
    return a;
}
__device__ __forceinline__ void cpa16(uint32_t dst, const void* src, bool ok) {
    asm volatile("cp.async.cg.shared.global [%0], [%1], 16, %2;"
                 :: "r"(dst), "l"(src), "r"(ok ? 16 : 0) : "memory");
}
__device__ __forceinline__ void cpa_commit() {
    asm volatile("cp.async.commit_group;" ::: "memory");
}
template <int N>
__device__ __forceinline__ void cpa_wait() {
    asm volatile("cp.async.wait_group %0;" :: "n"(N) : "memory");
}
__device__ __forceinline__ void ldsm4(uint32_t addr, uint32_t r[4]) {
    asm volatile("ldmatrix.sync.aligned.m8n8.x4.shared.b16 {%0,%1,%2,%3}, [%4];"
                 : "=r"(r[0]), "=r"(r[1]), "=r"(r[2]), "=r"(r[3]) : "r"(addr));
}
__device__ __forceinline__ void mma16816(float c[4], const uint32_t a[4],
                                         uint32_t b0, uint32_t b1) {
    asm volatile(
        "mma.sync.aligned.m16n8k16.row.col.f32.bf16.bf16.f32 "
        "{%0,%1,%2,%3},{%4,%5,%6,%7},{%8,%9},{%0,%1,%2,%3};"
        : "+f"(c[0]), "+f"(c[1]), "+f"(c[2]), "+f"(c[3])
        : "r"(a[0]), "r"(a[1]), "r"(a[2]), "r"(a[3]), "r"(b0), "r"(b1));
}

// ---------------------------------------------------------------------------
// Kernel 0: split fp32 -> bf16 hi/lo (round-5 version; proven 16.3us)
// ---------------------------------------------------------------------------
__device__ __forceinline__ void split4(float4 v, uint2& hi, uint2& lo) {
    __nv_bfloat16 h0 = __float2bfloat16(v.x), h1 = __float2bfloat16(v.y);
    __nv_bfloat16 h2 = __float2bfloat16(v.z), h3 = __float2bfloat16(v.w);
    __nv_bfloat16 l0 = __float2bfloat16(v.x - __bfloat162float(h0));
    __nv_bfloat16 l1 = __float2bfloat16(v.y - __bfloat162float(h1));
    __nv_bfloat16 l2 = __float2bfloat16(v.z - __bfloat162float(h2));
    __nv_bfloat16 l3 = __float2bfloat16(v.w - __bfloat162float(h3));
    hi.x = (uint32_t)__bfloat16_as_ushort(h0) | ((uint32_t)__bfloat16_as_ushort(h1) << 16);
    hi.y = (uint32_t)__bfloat16_as_ushort(h2) | ((uint32_t)__bfloat16_as_ushort(h3) << 16);
    lo.x = (uint32_t)__bfloat16_as_ushort(l0) | ((uint32_t)__bfloat16_as_ushort(l1) << 16);
    lo.y = (uint32_t)__bfloat16_as_ushort(l2) | ((uint32_t)__bfloat16_as_ushort(l3) << 16);
}

__global__ __launch_bounds__(256)
void split_kernel(const float* __restrict__ feat,
                  const float* __restrict__ Wself,
                  const float* __restrict__ Wneigh, int n)
{
    size_t nA4 = (size_t)n * DIM / 4;
    size_t nW4 = (size_t)2 * DIM * DIM / 4;   // 32768
    size_t tot = nA4 + nW4;
    for (size_t i = (size_t)blockIdx.x * blockDim.x + threadIdx.x; i < tot;
         i += (size_t)gridDim.x * blockDim.x) {
        float4 v; uint2 *hd, *ld;
        if (i < nA4) {
            v = ((const float4*)feat)[i];
            hd = (uint2*)g_ahi + i; ld = (uint2*)g_alo + i;
        } else {
            size_t j = i - nA4;
            const float* W = (j < 16384) ? Wself : Wneigh;
            size_t jj = (j < 16384) ? j : j - 16384;
            v = ((const float4*)W)[jj];
            hd = (uint2*)g_whi + j; ld = (uint2*)g_wlo + j;
        }
        uint2 hi, lo; split4(v, hi, lo);
        *hd = hi; *ld = lo;
    }
}

// ---------------------------------------------------------------------------
// Kernel 1: fused HMMA GEMM + top-k.
// CTA tile 128x256xK256, BK=32, 3 cp.async stages, 512 threads (16 warps).
// Inner loop restructured: load ALL fragments per k-step, then 3 passes of
// 16 independent-accumulator MMAs each (breaks acc dependency chains).
// ---------------------------------------------------------------------------
constexpr int RS      = 40;                     // smem row stride (bf16)
constexpr int A_TILE  = 128 * RS * 2;           // 10240 B
constexpr int B_TILE  = 256 * RS * 2;           // 20480 B
constexpr int STAGE   = 2 * A_TILE + 2 * B_TILE;// 61440 B
constexpr int GEMM_SMEM = 3 * STAGE;            // 184320 B (>= 128*260*4 tile)
constexpr int RS2     = 260;                    // fp32 tile stride (pad 4)
constexpr float ERRB  = 1e-3f;

__device__ __forceinline__ void load_stage(uint32_t sb, int kt, int row0,
                                           int mat, int n, int tid)
{
    {   // A: 128 rows x 32 k, hi+lo
        int row = tid >> 2, kc = (tid & 3) * 8;
        uint32_t soff = (uint32_t)(row * RS + kc) * 2;
        int gr = row0 + row;
        bool ok = gr < n;
        size_t aidx = (size_t)(ok ? gr : 0) * DIM + kt * 32 + kc;
        cpa16(sb + soff,          g_ahi + aidx, ok);
        cpa16(sb + A_TILE + soff, g_alo + aidx, ok);
    }
    #pragma unroll
    for (int h = 0; h < 2; h++) {   // B: 256 rows x 32 k, hi+lo
        int t = tid + h * 512;
        int row = t >> 2, kc = (t & 3) * 8;
        uint32_t soff = (uint32_t)(row * RS + kc) * 2;
        size_t bidx = (size_t)(mat * DIM + row) * DIM + kt * 32 + kc;
        cpa16(sb + 2 * A_TILE + soff,          g_whi + bidx, true);
        cpa16(sb + 2 * A_TILE + B_TILE + soff, g_wlo + bidx, true);
    }
}

__global__ __launch_bounds__(512, 1)
void gemm_topk_kernel(const float* __restrict__ feat,
                      const float* __restrict__ Wneigh,
                      const float* __restrict__ bneigh,
                      float* __restrict__ out, int n)
{
    extern __shared__ char smem[];
    const uint32_t sbase = smem_u32(smem);
    const int tid = threadIdx.x, lane = tid & 31, wid = tid >> 5;
    const int warp_m = wid & 3, warp_n = wid >> 2;
    const int mat = blockIdx.x;
    const int row0 = blockIdx.y * 128;

    float acc[2][8][4] = {};

    load_stage(sbase,         0, row0, mat, n, tid); cpa_commit();
    load_stage(sbase + STAGE, 1, row0, mat, n, tid); cpa_commit();

    #pragma unroll 1
    for (int kt = 0; kt < 8; kt++) {
        if (kt < 7) cpa_wait<1>(); else cpa_wait<0>();
        __syncthreads();
        if (kt < 6) {
            load_stage(sbase + ((kt + 2) % 3) * STAGE, kt + 2, row0, mat, n, tid);
            cpa_commit();
        }

        const uint32_t st = sbase + (kt % 3) * STAGE;
        #pragma unroll
        for (int ks = 0; ks < 2; ks++) {
            const int k0 = ks * 16;
            uint32_t ahi[2][4], alo[2][4], bhi[4][4], blo[4][4];
            #pragma unroll
            for (int mf = 0; mf < 2; mf++) {
                uint32_t ra = st + (uint32_t)((warp_m * 32 + mf * 16 + (lane & 15)) * RS
                                              + k0 + (lane >> 4) * 8) * 2;
                ldsm4(ra, ahi[mf]);
                ldsm4(ra + A_TILE, alo[mf]);
            }
            #pragma unroll
            for (int ng = 0; ng < 4; ng++) {
                uint32_t rb = st + 2 * A_TILE
                    + (uint32_t)((warp_n * 64 + ng * 16 + (lane >> 4) * 8 + (lane & 7)) * RS
                                 + k0 + ((lane >> 3) & 1) * 8) * 2;
                ldsm4(rb, bhi[ng]);
                ldsm4(rb + B_TILE, blo[ng]);
            }
            // pass 1: Ahi * Bhi — 16 independent accumulators
            #pragma unroll
            for (int mf = 0; mf < 2; mf++)
                #pragma unroll
                for (int nf = 0; nf < 8; nf++)
                    mma16816(acc[mf][nf], ahi[mf],
                             bhi[nf >> 1][(nf & 1) * 2], bhi[nf >> 1][(nf & 1) * 2 + 1]);
            // pass 2: Ahi * Blo
            #pragma unroll
            for (int mf = 0; mf < 2; mf++)
                #pragma unroll
                for (int nf = 0; nf < 8; nf++)
                    mma16816(acc[mf][nf], ahi[mf],
                             blo[nf >> 1][(nf & 1) * 2], blo[nf >> 1][(nf & 1) * 2 + 1]);
            // pass 3: Alo * Bhi
            #pragma unroll
            for (int mf = 0; mf < 2; mf++)
                #pragma unroll
                for (int nf = 0; nf < 8; nf++)
                    mma16816(acc[mf][nf], alo[mf],
                             bhi[nf >> 1][(nf & 1) * 2], bhi[nf >> 1][(nf & 1) * 2 + 1]);
        }
    }

    if (mat == 0) {
        // h_self straight to global
        #pragma unroll
        for (int nf = 0; nf < 8; nf++) {
            int col = warp_n * 64 + nf * 8 + (lane & 3) * 2;
            #pragma unroll
            for (int mf = 0; mf < 2; mf++) {
                int r0 = row0 + warp_m * 32 + mf * 16 + (lane >> 2);
                if (r0 < n)
                    *(float2*)(out + (size_t)r0 * DIM + col) =
                        make_float2(acc[mf][nf][0], acc[mf][nf][1]);
                int r1 = r0 + 8;
                if (r1 < n)
                    *(float2*)(out + (size_t)r1 * DIM + col) =
                        make_float2(acc[mf][nf][2], acc[mf][nf][3]);
            }
        }
        return;
    }

    // ---- mat == 1: feat_neigh + bias -> smem tile, then fused top-k ----
    __syncthreads();                      // done reading pipeline smem
    float* tile = (float*)smem;
    #pragma unroll
    for (int nf = 0; nf < 8; nf++) {
        int col = warp_n * 64 + nf * 8 + (lane & 3) * 2;
        float2 b = *(const float2*)(bneigh + col);
        #pragma unroll
        for (int mf = 0; mf < 2; mf++) {
            int r0 = warp_m * 32 + mf * 16 + (lane >> 2);
            tile[r0 * RS2 + col]     = acc[mf][nf][0] + b.x;
            tile[r0 * RS2 + col + 1] = acc[mf][nf][1] + b.y;
            int r1 = r0 + 8;
            tile[r1 * RS2 + col]     = acc[mf][nf][2] + b.x;
            tile[r1 * RS2 + col + 1] = acc[mf][nf][3] + b.y;
        }
    }
    __syncthreads();

    // each warp: 8 rows of top-32
    #pragma unroll 1
    for (int r8 = 0; r8 < 8; r8++) {
        const int lrow = wid * 8 + r8;
        const int grow = row0 + lrow;
        if (grow >= n) break;             // warp-uniform

        const float* srcr = tile + lrow * RS2;
        float v[8]; uint32_t u[8];
        #pragma unroll
        for (int i = 0; i < 8; i++) {
            v[i] = srcr[lane + i * 32];
            uint32_t s = __float_as_uint(v[i]);
            u[i] = (s & 0x80000000u) ? ~s : (s | 0x80000000u);
        }

        // radix select with early exit (count == 32 -> unique separation)
        uint32_t T = 0;
        #pragma unroll 1
        for (int bit = 31; bit >= 0; bit--) {
            uint32_t cand = T | (1u << bit);
            int c = 0;
            #pragma unroll
            for (int i = 0; i < 8; i++) c += (u[i] >= cand);
            c = __reduce_add_sync(0xffffffffu, c);
            if (c >= KSEL) { T = cand; if (c == KSEL) break; }
        }
        // v32 = approx value of the 32nd largest = min over selected
        float mn = __uint_as_float(0x7f800000);   // +inf
        #pragma unroll
        for (int i = 0; i < 8; i++)
            if (u[i] >= T) mn = fminf(mn, v[i]);
        #pragma unroll
        for (int off = 16; off; off >>= 1)
            mn = fminf(mn, __shfl_xor_sync(0xffffffffu, mn, off));
        const float v32 = mn;
        const float hi_thr = v32 + 2.f * ERRB;
        const float lo_thr = v32 - 2.f * ERRB;

        int cntS = 0, cntB = 0, bm = 0;
        #pragma unroll
        for (int i = 0; i < 8; i++) {
            bool sure = v[i] > hi_thr;
            bool bnd  = !sure && (v[i] >= lo_thr);
            cntS += sure; cntB += bnd;
            if (bnd) bm |= (1 << i);
        }
        cntS = __reduce_add_sync(0xffffffffu, cntS);
        int cntBw = __reduce_add_sync(0xffffffffu, cntB);
        const int need = KSEL - cntS;

        int picked = 0;
        float ex[8];
        const bool exact_path = (cntBw != need);
        if (exact_path) {
            // exact fp32 recompute for boundary elements (rare)
            const float* fr = feat + (size_t)grow * DIM;
            #pragma unroll 1
            for (int i = 0; i < 8; i++) {
                uint32_t bal = __ballot_sync(0xffffffffu, (bm >> i) & 1);
                while (bal) {
                    int owner = __ffs(bal) - 1; bal &= bal - 1;
                    int col = owner + i * 32;
                    const float* wr = Wneigh + (size_t)col * DIM;
                    float p = 0.f;
                    #pragma unroll
                    for (int j = 0; j < 8; j++)
                        p = fmaf(fr[lane + j * 32], wr[lane + j * 32], p);
                    #pragma unroll
                    for (int off = 16; off; off >>= 1)
                        p += __shfl_xor_sync(0xffffffffu, p, off);
                    if (lane == owner) ex[i] = p + bneigh[col];
                }
            }
            int rem = need, avail = bm;
            while (rem > 0) {
                float bv = __uint_as_float(0xff800000);   // -inf
                int bc = 0x7fffffff;
                #pragma unroll
                for (int i = 0; i < 8; i++)
                    if ((avail >> i) & 1) {
                        float e = ex[i]; int c = lane + i * 32;
                        if (e > bv || (e == bv && c < bc)) { bv = e; bc = c; }
                    }
                #pragma unroll
                for (int off = 16; off; off >>= 1) {
                    float ov = __shfl_xor_sync(0xffffffffu, bv, off);
                    int   oc = __shfl_xor_sync(0xffffffffu, bc, off);
                    if (ov > bv || (ov == bv && oc < bc)) { bv = ov; bc = oc; }
                }
                if (lane == (bc & 31)) {
                    avail  &= ~(1 << (bc >> 5));
                    picked |=  (1 << (bc >> 5));
                }
                rem--;
            }
        } else {
            picked = bm;
        }

        // packed compaction write: val(24b rounded) | col(8b)
        const uint32_t ltmask = (1u << lane) - 1u;
        int basep = 0;
        uint32_t* __restrict__ dst = g_topk + (size_t)grow * KSEL;
        #pragma unroll
        for (int i = 0; i < 8; i++) {
            bool sure = v[i] > hi_thr;
            bool pick = (picked >> i) & 1;
            bool sel = sure || pick;
            float wv = (pick && exact_path) ? ex[i] : v[i];
            uint32_t bs = __ballot_sync(0xffffffffu, sel);
            if (sel) {
                int pos = basep + __popc(bs & ltmask);
                uint32_t bits = (__float_as_uint(wv) + 0x80u) & 0xFFFFFF00u;
                dst[pos] = bits | (uint32_t)(lane + i * 32);
            }
            basep += __popc(bs);
        }
    }
}

// ---------------------------------------------------------------------------
// Kernel 2: CSR SpMM (round-5 version; best so far).
// One warp per dst row; single smem accumulator, converged-warp RMW chain.
// ---------------------------------------------------------------------------
__global__ __launch_bounds__(256)
void spmm_kernel(const int* __restrict__ indices,
                 const int* __restrict__ indptr,
                 float* __restrict__ out, int n)
{
    __shared__ float accs[8][DIM];
    const int warp = threadIdx.x >> 5;
    const int lane = threadIdx.x & 31;
    const int row = blockIdx.x * 8 + warp;
    if (row >= n) return;

    volatile float* a = accs[warp];
    #pragma unroll
    for (int i = 0; i < 8; i++) a[lane + i * 32] = 0.f;
    __syncwarp();

    const int s = indptr[row];
    const int e = indptr[row + 1];
    int j = s;
    for (; j + 4 <= e; j += 4) {
        int i0 = indices[j], i1 = indices[j+1], i2 = indices[j+2], i3 = indices[j+3];
        uint32_t p0 = __ldg(&g_topk[(size_t)i0 * KSEL + lane]);
        uint32_t p1 = __ldg(&g_topk[(size_t)i1 * KSEL + lane]);
        uint32_t p2 = __ldg(&g_topk[(size_t)i2 * KSEL + lane]);
        uint32_t p3 = __ldg(&g_topk[(size_t)i3 * KSEL + lane]);
        a[p0 & 0xFF] += __uint_as_float(p0 & 0xFFFFFF00u);
        a[p1 & 0xFF] += __uint_as_float(p1 & 0xFFFFFF00u);
        a[p2 & 0xFF] += __uint_as_float(p2 & 0xFFFFFF00u);
        a[p3 & 0xFF] += __uint_as_float(p3 & 0xFFFFFF00u);
    }
    for (; j < e; j++) {
        uint32_t p0 = __ldg(&g_topk[(size_t)indices[j] * KSEL + lane]);
        a[p0 & 0xFF] += __uint_as_float(p0 & 0xFFFFFF00u);
    }
    __syncwarp();

    #pragma unroll
    for (int i = 0; i < 8; i++) {
        int c = lane + i * 32;
        out[(size_t)row * DIM + c] += a[c];
    }
}

// ---------------------------------------------------------------------------
extern "C" void kernel_launch(void* const* d_in, const int* in_sizes, int n_in,
                              void* d_out, int out_size)
{
    const float* feat    = (const float*)d_in[0];
    const float* Wself   = (const float*)d_in[1];
    const float* Wneigh  = (const float*)d_in[2];
    const float* bneigh  = (const float*)d_in[3];
    const int*   indices = (const int*)d_in[4];
    const int*   indptr  = (const int*)d_in[5];
    float* out = (float*)d_out;

    const int n = in_sizes[0] / DIM;   // 50000

    cudaFuncSetAttribute(gemm_topk_kernel,
                         cudaFuncAttributeMaxDynamicSharedMemorySize, GEMM_SMEM);

    // 0) fp32 -> bf16 hi/lo splits
    split_kernel<<<1024, 256>>>(feat, Wself, Wneigh, n);

    // 1) fused GEMM + top-k: h_self -> out, top-32(feat_neigh+b) -> g_topk
    dim3 ggrid(2, (n + 127) / 128);
    gemm_topk_kernel<<<ggrid, 512, GEMM_SMEM>>>(feat, Wneigh, bneigh, out, n);

    // 2) SpMM accumulate onto h_self
    int blocks_rows = (n + 7) / 8;
    spmm_kernel<<<blocks_rows, 256>>>(indices, indptr, out, n);
}

// round 8
// speedup vs baseline: 1.0756x; 1.0228x over previous
#include <cuda_runtime.h>
#include <cuda_bf16.h>
#include <cstdint>

constexpr int N_NODES = 50000;
constexpr int DIM     = 256;   // IN == OUT
constexpr int KSEL    = 32;

// ---------------------------------------------------------------------------
// Device-global scratch (allocation-free rule)
// ---------------------------------------------------------------------------
__device__ uint32_t g_topk[(size_t)N_NODES * KSEL]; // packed val(24b)|col(8b)
__device__ uint16_t g_ahi [(size_t)N_NODES * DIM];  // feat hi (bf16 bits)
__device__ uint16_t g_alo [(size_t)N_NODES * DIM];  // feat lo
__device__ uint16_t g_whi [2 * DIM * DIM];          // [Wself;Wneigh] hi
__device__ uint16_t g_wlo [2 * DIM * DIM];          // [Wself;Wneigh] lo

// ---------------------------------------------------------------------------
// helpers
// ---------------------------------------------------------------------------
__device__ __forceinline__ uint32_t smem_u32(const void* p) {
    uint32_t a;
    asm("{ .reg .u64 t; cvta.to.shared.u64 t, %1; cvt.u32.u64 %0, t; }"
        : "=r"(a) : "l"(p));
    return a;
}
__device__ __forceinline__ void cpa16(uint32_t dst, const void* src, bool ok) {
    asm volatile("cp.async.cg.shared.global [%0], [%1], 16, %2;"
                 :: "r"(dst), "l"(src), "r"(ok ? 16 : 0) : "memory");
}
__device__ __forceinline__ void cpa_commit() {
    asm volatile("cp.async.commit_group;" ::: "memory");
}
template <int N>
__device__ __forceinline__ void cpa_wait() {
    asm volatile("cp.async.wait_group %0;" :: "n"(N) : "memory");
}
__device__ __forceinline__ void ldsm4(uint32_t addr, uint32_t r[4]) {
    asm volatile("ldmatrix.sync.aligned.m8n8.x4.shared.b16 {%0,%1,%2,%3}, [%4];"
                 : "=r"(r[0]), "=r"(r[1]), "=r"(r[2]), "=r"(r[3]) : "r"(addr));
}
__device__ __forceinline__ void mma16816(float c[4], const uint32_t a[4],
                                         uint32_t b0, uint32_t b1) {
    asm volatile(
        "mma.sync.aligned.m16n8k16.row.col.f32.bf16.bf16.f32 "
        "{%0,%1,%2,%3},{%4,%5,%6,%7},{%8,%9},{%0,%1,%2,%3};"
        : "+f"(c[0]), "+f"(c[1]), "+f"(c[2]), "+f"(c[3])
        : "r"(a[0]), "r"(a[1]), "r"(a[2]), "r"(a[3]), "r"(b0), "r"(b1));
}

// ---------------------------------------------------------------------------
// Kernel 0: split fp32 -> bf16 hi/lo (round-5 version; proven 16.3us)
// ---------------------------------------------------------------------------
__device__ __forceinline__ void split4(float4 v, uint2& hi, uint2& lo) {
    __nv_bfloat16 h0 = __float2bfloat16(v.x), h1 = __float2bfloat16(v.y);
    __nv_bfloat16 h2 = __float2bfloat16(v.z), h3 = __float2bfloat16(v.w);
    __nv_bfloat16 l0 = __float2bfloat16(v.x - __bfloat162float(h0));
    __nv_bfloat16 l1 = __float2bfloat16(v.y - __bfloat162float(h1));
    __nv_bfloat16 l2 = __float2bfloat16(v.z - __bfloat162float(h2));
    __nv_bfloat16 l3 = __float2bfloat16(v.w - __bfloat162float(h3));
    hi.x = (uint32_t)__bfloat16_as_ushort(h0) | ((uint32_t)__bfloat16_as_ushort(h1) << 16);
    hi.y = (uint32_t)__bfloat16_as_ushort(h2) | ((uint32_t)__bfloat16_as_ushort(h3) << 16);
    lo.x = (uint32_t)__bfloat16_as_ushort(l0) | ((uint32_t)__bfloat16_as_ushort(l1) << 16);
    lo.y = (uint32_t)__bfloat16_as_ushort(l2) | ((uint32_t)__bfloat16_as_ushort(l3) << 16);
}

__global__ __launch_bounds__(256)
void split_kernel(const float* __restrict__ feat,
                  const float* __restrict__ Wself,
                  const float* __restrict__ Wneigh, int n)
{
    size_t nA4 = (size_t)n * DIM / 4;
    size_t nW4 = (size_t)2 * DIM * DIM / 4;   // 32768
    size_t tot = nA4 + nW4;
    for (size_t i = (size_t)blockIdx.x * blockDim.x + threadIdx.x; i < tot;
         i += (size_t)gridDim.x * blockDim.x) {
        float4 v; uint2 *hd, *ld;
        if (i < nA4) {
            v = ((const float4*)feat)[i];
            hd = (uint2*)g_ahi + i; ld = (uint2*)g_alo + i;
        } else {
            size_t j = i - nA4;
            const float* W = (j < 16384) ? Wself : Wneigh;
            size_t jj = (j < 16384) ? j : j - 16384;
            v = ((const float4*)W)[jj];
            hd = (uint2*)g_whi + j; ld = (uint2*)g_wlo + j;
        }
        uint2 hi, lo; split4(v, hi, lo);
        *hd = hi; *ld = lo;
    }
}

// ---------------------------------------------------------------------------
// Kernel 1: fused HMMA GEMM + top-k.
// CTA tile 128x256xK256, BK=32, 3 cp.async stages, 512 threads (16 warps).
// Round-5 inner loop order (proven fastest).
// mat=0 (h_self): 2 split passes (Ahi*Bhi + Ahi*Blo) — output tolerance only.
// mat=1 (feat_neigh): 3 passes (+ Alo*Bhi) — feeds top-k selection.
// ---------------------------------------------------------------------------
constexpr int RS      = 40;                     // smem row stride (bf16)
constexpr int A_TILE  = 128 * RS * 2;           // 10240 B
constexpr int B_TILE  = 256 * RS * 2;           // 20480 B
constexpr int STAGE   = 2 * A_TILE + 2 * B_TILE;// 61440 B
constexpr int GEMM_SMEM = 3 * STAGE;            // 184320 B (>= 128*260*4 tile)
constexpr int RS2     = 260;                    // fp32 tile stride (pad 4)
constexpr float ERRB  = 1e-3f;

__device__ __forceinline__ void load_stage(uint32_t sb, int kt, int row0,
                                           int mat, int n, int tid)
{
    {   // A: 128 rows x 32 k, hi+lo
        int row = tid >> 2, kc = (tid & 3) * 8;
        uint32_t soff = (uint32_t)(row * RS + kc) * 2;
        int gr = row0 + row;
        bool ok = gr < n;
        size_t aidx = (size_t)(ok ? gr : 0) * DIM + kt * 32 + kc;
        cpa16(sb + soff,          g_ahi + aidx, ok);
        cpa16(sb + A_TILE + soff, g_alo + aidx, ok);
    }
    #pragma unroll
    for (int h = 0; h < 2; h++) {   // B: 256 rows x 32 k, hi+lo
        int t = tid + h * 512;
        int row = t >> 2, kc = (t & 3) * 8;
        uint32_t soff = (uint32_t)(row * RS + kc) * 2;
        size_t bidx = (size_t)(mat * DIM + row) * DIM + kt * 32 + kc;
        cpa16(sb + 2 * A_TILE + soff,          g_whi + bidx, true);
        cpa16(sb + 2 * A_TILE + B_TILE + soff, g_wlo + bidx, true);
    }
}

__global__ __launch_bounds__(512, 1)
void gemm_topk_kernel(const float* __restrict__ feat,
                      const float* __restrict__ Wneigh,
                      const float* __restrict__ bneigh,
                      float* __restrict__ out, int n)
{
    extern __shared__ char smem[];
    const uint32_t sbase = smem_u32(smem);
    const int tid = threadIdx.x, lane = tid & 31, wid = tid >> 5;
    const int warp_m = wid & 3, warp_n = wid >> 2;
    const int mat = blockIdx.x;
    const bool third_pass = (mat == 1);
    const int row0 = blockIdx.y * 128;

    float acc[2][8][4] = {};

    load_stage(sbase,         0, row0, mat, n, tid); cpa_commit();
    load_stage(sbase + STAGE, 1, row0, mat, n, tid); cpa_commit();

    #pragma unroll 1
    for (int kt = 0; kt < 8; kt++) {
        if (kt < 7) cpa_wait<1>(); else cpa_wait<0>();
        __syncthreads();
        if (kt < 6) {
            load_stage(sbase + ((kt + 2) % 3) * STAGE, kt + 2, row0, mat, n, tid);
            cpa_commit();
        }

        const uint32_t st = sbase + (kt % 3) * STAGE;
        #pragma unroll
        for (int ks = 0; ks < 2; ks++) {
            const int k0 = ks * 16;
            uint32_t ahi[2][4], alo[2][4];
            #pragma unroll
            for (int mf = 0; mf < 2; mf++) {
                uint32_t ra = st + (uint32_t)((warp_m * 32 + mf * 16 + (lane & 15)) * RS
                                              + k0 + (lane >> 4) * 8) * 2;
                ldsm4(ra, ahi[mf]);
                ldsm4(ra + A_TILE, alo[mf]);
            }
            #pragma unroll
            for (int ng = 0; ng < 4; ng++) {
                uint32_t bhi4[4], blo4[4];
                uint32_t rb = st + 2 * A_TILE
                    + (uint32_t)((warp_n * 64 + ng * 16 + (lane >> 4) * 8 + (lane & 7)) * RS
                                 + k0 + ((lane >> 3) & 1) * 8) * 2;
                ldsm4(rb, bhi4);
                ldsm4(rb + B_TILE, blo4);
                #pragma unroll
                for (int sub = 0; sub < 2; sub++) {
                    int nf = ng * 2 + sub;
                    #pragma unroll
                    for (int mf = 0; mf < 2; mf++) {
                        mma16816(acc[mf][nf], ahi[mf], bhi4[sub * 2], bhi4[sub * 2 + 1]);
                        mma16816(acc[mf][nf], ahi[mf], blo4[sub * 2], blo4[sub * 2 + 1]);
                        if (third_pass)
                            mma16816(acc[mf][nf], alo[mf], bhi4[sub * 2], bhi4[sub * 2 + 1]);
                    }
                }
            }
        }
    }

    if (mat == 0) {
        // h_self straight to global
        #pragma unroll
        for (int nf = 0; nf < 8; nf++) {
            int col = warp_n * 64 + nf * 8 + (lane & 3) * 2;
            #pragma unroll
            for (int mf = 0; mf < 2; mf++) {
                int r0 = row0 + warp_m * 32 + mf * 16 + (lane >> 2);
                if (r0 < n)
                    *(float2*)(out + (size_t)r0 * DIM + col) =
                        make_float2(acc[mf][nf][0], acc[mf][nf][1]);
                int r1 = r0 + 8;
                if (r1 < n)
                    *(float2*)(out + (size_t)r1 * DIM + col) =
                        make_float2(acc[mf][nf][2], acc[mf][nf][3]);
            }
        }
        return;
    }

    // ---- mat == 1: feat_neigh + bias -> smem tile, then fused top-k ----
    __syncthreads();                      // done reading pipeline smem
    float* tile = (float*)smem;
    #pragma unroll
    for (int nf = 0; nf < 8; nf++) {
        int col = warp_n * 64 + nf * 8 + (lane & 3) * 2;
        float2 b = *(const float2*)(bneigh + col);
        #pragma unroll
        for (int mf = 0; mf < 2; mf++) {
            int r0 = warp_m * 32 + mf * 16 + (lane >> 2);
            tile[r0 * RS2 + col]     = acc[mf][nf][0] + b.x;
            tile[r0 * RS2 + col + 1] = acc[mf][nf][1] + b.y;
            int r1 = r0 + 8;
            tile[r1 * RS2 + col]     = acc[mf][nf][2] + b.x;
            tile[r1 * RS2 + col + 1] = acc[mf][nf][3] + b.y;
        }
    }
    __syncthreads();

    // each warp: 8 rows of top-32
    #pragma unroll 1
    for (int r8 = 0; r8 < 8; r8++) {
        const int lrow = wid * 8 + r8;
        const int grow = row0 + lrow;
        if (grow >= n) break;             // warp-uniform

        const float* srcr = tile + lrow * RS2;
        float v[8]; uint32_t u[8];
        #pragma unroll
        for (int i = 0; i < 8; i++) {
            v[i] = srcr[lane + i * 32];
            uint32_t s = __float_as_uint(v[i]);
            u[i] = (s & 0x80000000u) ? ~s : (s | 0x80000000u);
        }

        // radix select with early exit (count == 32 -> unique separation)
        uint32_t T = 0;
        #pragma unroll 1
        for (int bit = 31; bit >= 0; bit--) {
            uint32_t cand = T | (1u << bit);
            int c = 0;
            #pragma unroll
            for (int i = 0; i < 8; i++) c += (u[i] >= cand);
            c = __reduce_add_sync(0xffffffffu, c);
            if (c >= KSEL) { T = cand; if (c == KSEL) break; }
        }
        // v32 = approx value of the 32nd largest = min over selected
        float mn = __uint_as_float(0x7f800000);   // +inf
        #pragma unroll
        for (int i = 0; i < 8; i++)
            if (u[i] >= T) mn = fminf(mn, v[i]);
        #pragma unroll
        for (int off = 16; off; off >>= 1)
            mn = fminf(mn, __shfl_xor_sync(0xffffffffu, mn, off));
        const float v32 = mn;
        const float hi_thr = v32 + 2.f * ERRB;
        const float lo_thr = v32 - 2.f * ERRB;

        int cntS = 0, cntB = 0, bm = 0;
        #pragma unroll
        for (int i = 0; i < 8; i++) {
            bool sure = v[i] > hi_thr;
            bool bnd  = !sure && (v[i] >= lo_thr);
            cntS += sure; cntB += bnd;
            if (bnd) bm |= (1 << i);
        }
        cntS = __reduce_add_sync(0xffffffffu, cntS);
        int cntBw = __reduce_add_sync(0xffffffffu, cntB);
        const int need = KSEL - cntS;

        int picked = 0;
        float ex[8];
        const bool exact_path = (cntBw != need);
        if (exact_path) {
            // exact fp32 recompute for boundary elements (rare)
            const float* fr = feat + (size_t)grow * DIM;
            #pragma unroll 1
            for (int i = 0; i < 8; i++) {
                uint32_t bal = __ballot_sync(0xffffffffu, (bm >> i) & 1);
                while (bal) {
                    int owner = __ffs(bal) - 1; bal &= bal - 1;
                    int col = owner + i * 32;
                    const float* wr = Wneigh + (size_t)col * DIM;
                    float p = 0.f;
                    #pragma unroll
                    for (int j = 0; j < 8; j++)
                        p = fmaf(fr[lane + j * 32], wr[lane + j * 32], p);
                    #pragma unroll
                    for (int off = 16; off; off >>= 1)
                        p += __shfl_xor_sync(0xffffffffu, p, off);
                    if (lane == owner) ex[i] = p + bneigh[col];
                }
            }
            int rem = need, avail = bm;
            while (rem > 0) {
                float bv = __uint_as_float(0xff800000);   // -inf
                int bc = 0x7fffffff;
                #pragma unroll
                for (int i = 0; i < 8; i++)
                    if ((avail >> i) & 1) {
                        float e = ex[i]; int c = lane + i * 32;
                        if (e > bv || (e == bv && c < bc)) { bv = e; bc = c; }
                    }
                #pragma unroll
                for (int off = 16; off; off >>= 1) {
                    float ov = __shfl_xor_sync(0xffffffffu, bv, off);
                    int   oc = __shfl_xor_sync(0xffffffffu, bc, off);
                    if (ov > bv || (ov == bv && oc < bc)) { bv = ov; bc = oc; }
                }
                if (lane == (bc & 31)) {
                    avail  &= ~(1 << (bc >> 5));
                    picked |=  (1 << (bc >> 5));
                }
                rem--;
            }
        } else {
            picked = bm;
        }

        // packed compaction write: val(24b rounded) | col(8b)
        const uint32_t ltmask = (1u << lane) - 1u;
        int basep = 0;
        uint32_t* __restrict__ dst = g_topk + (size_t)grow * KSEL;
        #pragma unroll
        for (int i = 0; i < 8; i++) {
            bool sure = v[i] > hi_thr;
            bool pick = (picked >> i) & 1;
            bool sel = sure || pick;
            float wv = (pick && exact_path) ? ex[i] : v[i];
            uint32_t bs = __ballot_sync(0xffffffffu, sel);
            if (sel) {
                int pos = basep + __popc(bs & ltmask);
                uint32_t bits = (__float_as_uint(wv) + 0x80u) & 0xFFFFFF00u;
                dst[pos] = bits | (uint32_t)(lane + i * 32);
            }
            basep += __popc(bs);
        }
    }
}

// ---------------------------------------------------------------------------
// Kernel 2: CSR SpMM (round-5 version; best so far).
// One warp per dst row; single smem accumulator, converged-warp RMW chain.
// ---------------------------------------------------------------------------
__global__ __launch_bounds__(256)
void spmm_kernel(const int* __restrict__ indices,
                 const int* __restrict__ indptr,
                 float* __restrict__ out, int n)
{
    __shared__ float accs[8][DIM];
    const int warp = threadIdx.x >> 5;
    const int lane = threadIdx.x & 31;
    const int row = blockIdx.x * 8 + warp;
    if (row >= n) return;

    volatile float* a = accs[warp];
    #pragma unroll
    for (int i = 0; i < 8; i++) a[lane + i * 32] = 0.f;
    __syncwarp();

    const int s = indptr[row];
    const int e = indptr[row + 1];
    int j = s;
    for (; j + 4 <= e; j += 4) {
        int i0 = indices[j], i1 = indices[j+1], i2 = indices[j+2], i3 = indices[j+3];
        uint32_t p0 = __ldg(&g_topk[(size_t)i0 * KSEL + lane]);
        uint32_t p1 = __ldg(&g_topk[(size_t)i1 * KSEL + lane]);
        uint32_t p2 = __ldg(&g_topk[(size_t)i2 * KSEL + lane]);
        uint32_t p3 = __ldg(&g_topk[(size_t)i3 * KSEL + lane]);
        a[p0 & 0xFF] += __uint_as_float(p0 & 0xFFFFFF00u);
        a[p1 & 0xFF] += __uint_as_float(p1 & 0xFFFFFF00u);
        a[p2 & 0xFF] += __uint_as_float(p2 & 0xFFFFFF00u);
        a[p3 & 0xFF] += __uint_as_float(p3 & 0xFFFFFF00u);
    }
    for (; j < e; j++) {
        uint32_t p0 = __ldg(&g_topk[(size_t)indices[j] * KSEL + lane]);
        a[p0 & 0xFF] += __uint_as_float(p0 & 0xFFFFFF00u);
    }
    __syncwarp();

    #pragma unroll
    for (int i = 0; i < 8; i++) {
        int c = lane + i * 32;
        out[(size_t)row * DIM + c] += a[c];
    }
}

// ---------------------------------------------------------------------------
extern "C" void kernel_launch(void* const* d_in, const int* in_sizes, int n_in,
                              void* d_out, int out_size)
{
    const float* feat    = (const float*)d_in[0];
    const float* Wself   = (const float*)d_in[1];
    const float* Wneigh  = (const float*)d_in[2];
    const float* bneigh  = (const float*)d_in[3];
    const int*   indices = (const int*)d_in[4];
    const int*   indptr  = (const int*)d_in[5];
    float* out = (float*)d_out;

    const int n = in_sizes[0] / DIM;   // 50000

    cudaFuncSetAttribute(gemm_topk_kernel,
                         cudaFuncAttributeMaxDynamicSharedMemorySize, GEMM_SMEM);

    // 0) fp32 -> bf16 hi/lo splits
    split_kernel<<<1024, 256>>>(feat, Wself, Wneigh, n);

    // 1) fused GEMM + top-k: h_self -> out, top-32(feat_neigh+b) -> g_topk
    dim3 ggrid(2, (n + 127) / 128);
    gemm_topk_kernel<<<ggrid, 512, GEMM_SMEM>>>(feat, Wneigh, bneigh, out, n);

    // 2) SpMM accumulate onto h_self
    int blocks_rows = (n + 7) / 8;
    spmm_kernel<<<blocks_rows, 256>>>(indices, indptr, out, n);
}

// round 9
// speedup vs baseline: 1.4532x; 1.3511x over previous
#include <cuda_runtime.h>
#include <cuda_fp16.h>
#include <cstdint>

constexpr int N_NODES = 50000;
constexpr int DIM     = 256;   // IN == OUT
constexpr int KSEL    = 32;

// ---------------------------------------------------------------------------
// Device-global scratch (allocation-free rule)
// ---------------------------------------------------------------------------
__device__ uint32_t g_topk[(size_t)N_NODES * KSEL]; // packed val(24b)|col(8b)
__device__ uint16_t g_a [(size_t)N_NODES * DIM];    // feat (fp16 bits)
__device__ uint16_t g_w [2 * DIM * DIM];            // [Wself;Wneigh] (fp16)

// ---------------------------------------------------------------------------
// helpers
// ---------------------------------------------------------------------------
__device__ __forceinline__ uint32_t smem_u32(const void* p) {
    uint32_t a;
    asm("{ .reg .u64 t; cvta.to.shared.u64 t, %1; cvt.u32.u64 %0, t; }"
        : "=r"(a) : "l"(p));
    return a;
}
__device__ __forceinline__ void cpa16(uint32_t dst, const void* src, bool ok) {
    asm volatile("cp.async.cg.shared.global [%0], [%1], 16, %2;"
                 :: "r"(dst), "l"(src), "r"(ok ? 16 : 0) : "memory");
}
__device__ __forceinline__ void cpa_commit() {
    asm volatile("cp.async.commit_group;" ::: "memory");
}
template <int N>
__device__ __forceinline__ void cpa_wait() {
    asm volatile("cp.async.wait_group %0;" :: "n"(N) : "memory");
}
__device__ __forceinline__ void ldsm4(uint32_t addr, uint32_t r[4]) {
    asm volatile("ldmatrix.sync.aligned.m8n8.x4.shared.b16 {%0,%1,%2,%3}, [%4];"
                 : "=r"(r[0]), "=r"(r[1]), "=r"(r[2]), "=r"(r[3]) : "r"(addr));
}
__device__ __forceinline__ void mma16816(float c[4], const uint32_t a[4],
                                         uint32_t b0, uint32_t b1) {
    asm volatile(
        "mma.sync.aligned.m16n8k16.row.col.f32.f16.f16.f32 "
        "{%0,%1,%2,%3},{%4,%5,%6,%7},{%8,%9},{%0,%1,%2,%3};"
        : "+f"(c[0]), "+f"(c[1]), "+f"(c[2]), "+f"(c[3])
        : "r"(a[0]), "r"(a[1]), "r"(a[2]), "r"(a[3]), "r"(b0), "r"(b1));
}

// ---------------------------------------------------------------------------
// Kernel 0: convert fp32 -> fp16 for feat and both weight matrices
// ---------------------------------------------------------------------------
__global__ __launch_bounds__(256)
void split_kernel(const float* __restrict__ feat,
                  const float* __restrict__ Wself,
                  const float* __restrict__ Wneigh, int n)
{
    size_t nA4 = (size_t)n * DIM / 4;
    size_t nW4 = (size_t)2 * DIM * DIM / 4;   // 32768
    size_t tot = nA4 + nW4;
    for (size_t i = (size_t)blockIdx.x * blockDim.x + threadIdx.x; i < tot;
         i += (size_t)gridDim.x * blockDim.x) {
        float4 v; uint2* hd;
        if (i < nA4) {
            v = ((const float4*)feat)[i];
            hd = (uint2*)g_a + i;
        } else {
            size_t j = i - nA4;
            const float* W = (j < 16384) ? Wself : Wneigh;
            size_t jj = (j < 16384) ? j : j - 16384;
            v = ((const float4*)W)[jj];
            hd = (uint2*)g_w + j;
        }
        uint2 h;
        h.x = (uint32_t)__half_as_ushort(__float2half_rn(v.x))
            | ((uint32_t)__half_as_ushort(__float2half_rn(v.y)) << 16);
        h.y = (uint32_t)__half_as_ushort(__float2half_rn(v.z))
            | ((uint32_t)__half_as_ushort(__float2half_rn(v.w)) << 16);
        *hd = h;
    }
}

// ---------------------------------------------------------------------------
// Kernel 1: fused single-pass fp16 HMMA GEMM + top-k.
// CTA tile 128x256xK256, BK=32, 3 cp.async stages, 512 threads (16 warps).
// mat=0: h_self -> out.  mat=1: feat_neigh+bias -> smem tile -> top-32.
// Selection protected by error window + exact fp32 boundary recompute.
// ---------------------------------------------------------------------------
constexpr int RS      = 40;                     // smem row stride (fp16 elems)
constexpr int A_TILE  = 128 * RS * 2;           // 10240 B
constexpr int B_TILE  = 256 * RS * 2;           // 20480 B
constexpr int STAGE   = A_TILE + B_TILE;        // 30720 B
constexpr int RS2     = 260;                    // fp32 tile stride (pad 4)
constexpr int TILE_F32 = 128 * RS2 * 4;         // 133120 B
constexpr int GEMM_SMEM = (3 * STAGE > TILE_F32) ? 3 * STAGE : TILE_F32;
constexpr float ERRB  = 1.5e-3f;

__device__ __forceinline__ void load_stage(uint32_t sb, int kt, int row0,
                                           int mat, int n, int tid)
{
    {   // A: 128 rows x 32 k (512 chunks of 16B, 1 per thread)
        int row = tid >> 2, kc = (tid & 3) * 8;
        uint32_t soff = (uint32_t)(row * RS + kc) * 2;
        int gr = row0 + row;
        bool ok = gr < n;
        size_t aidx = (size_t)(ok ? gr : 0) * DIM + kt * 32 + kc;
        cpa16(sb + soff, g_a + aidx, ok);
    }
    #pragma unroll
    for (int h = 0; h < 2; h++) {   // B: 256 rows x 32 k (1024 chunks)
        int t = tid + h * 512;
        int row = t >> 2, kc = (t & 3) * 8;
        uint32_t soff = (uint32_t)(row * RS + kc) * 2;
        size_t bidx = (size_t)(mat * DIM + row) * DIM + kt * 32 + kc;
        cpa16(sb + A_TILE + soff, g_w + bidx, true);
    }
}

__global__ __launch_bounds__(512, 1)
void gemm_topk_kernel(const float* __restrict__ feat,
                      const float* __restrict__ Wneigh,
                      const float* __restrict__ bneigh,
                      float* __restrict__ out, int n)
{
    extern __shared__ char smem[];
    const uint32_t sbase = smem_u32(smem);
    const int tid = threadIdx.x, lane = tid & 31, wid = tid >> 5;
    const int warp_m = wid & 3, warp_n = wid >> 2;
    const int mat = blockIdx.x;
    const int row0 = blockIdx.y * 128;

    float acc[2][8][4] = {};

    load_stage(sbase,         0, row0, mat, n, tid); cpa_commit();
    load_stage(sbase + STAGE, 1, row0, mat, n, tid); cpa_commit();

    #pragma unroll 1
    for (int kt = 0; kt < 8; kt++) {
        if (kt < 7) cpa_wait<1>(); else cpa_wait<0>();
        __syncthreads();
        if (kt < 6) {
            load_stage(sbase + ((kt + 2) % 3) * STAGE, kt + 2, row0, mat, n, tid);
            cpa_commit();
        }

        const uint32_t st = sbase + (kt % 3) * STAGE;
        #pragma unroll
        for (int ks = 0; ks < 2; ks++) {
            const int k0 = ks * 16;
            uint32_t afr[2][4];
            #pragma unroll
            for (int mf = 0; mf < 2; mf++) {
                uint32_t ra = st + (uint32_t)((warp_m * 32 + mf * 16 + (lane & 15)) * RS
                                              + k0 + (lane >> 4) * 8) * 2;
                ldsm4(ra, afr[mf]);
            }
            #pragma unroll
            for (int ng = 0; ng < 4; ng++) {
                uint32_t bfr[4];
                uint32_t rb = st + A_TILE
                    + (uint32_t)((warp_n * 64 + ng * 16 + (lane >> 4) * 8 + (lane & 7)) * RS
                                 + k0 + ((lane >> 3) & 1) * 8) * 2;
                ldsm4(rb, bfr);
                #pragma unroll
                for (int sub = 0; sub < 2; sub++) {
                    int nf = ng * 2 + sub;
                    #pragma unroll
                    for (int mf = 0; mf < 2; mf++)
                        mma16816(acc[mf][nf], afr[mf], bfr[sub * 2], bfr[sub * 2 + 1]);
                }
            }
        }
    }

    if (mat == 0) {
        // h_self straight to global
        #pragma unroll
        for (int nf = 0; nf < 8; nf++) {
            int col = warp_n * 64 + nf * 8 + (lane & 3) * 2;
            #pragma unroll
            for (int mf = 0; mf < 2; mf++) {
                int r0 = row0 + warp_m * 32 + mf * 16 + (lane >> 2);
                if (r0 < n)
                    *(float2*)(out + (size_t)r0 * DIM + col) =
                        make_float2(acc[mf][nf][0], acc[mf][nf][1]);
                int r1 = r0 + 8;
                if (r1 < n)
                    *(float2*)(out + (size_t)r1 * DIM + col) =
                        make_float2(acc[mf][nf][2], acc[mf][nf][3]);
            }
        }
        return;
    }

    // ---- mat == 1: feat_neigh + bias -> smem tile, then fused top-k ----
    __syncthreads();                      // done reading pipeline smem
    float* tile = (float*)smem;
    #pragma unroll
    for (int nf = 0; nf < 8; nf++) {
        int col = warp_n * 64 + nf * 8 + (lane & 3) * 2;
        float2 b = *(const float2*)(bneigh + col);
        #pragma unroll
        for (int mf = 0; mf < 2; mf++) {
            int r0 = warp_m * 32 + mf * 16 + (lane >> 2);
            tile[r0 * RS2 + col]     = acc[mf][nf][0] + b.x;
            tile[r0 * RS2 + col + 1] = acc[mf][nf][1] + b.y;
            int r1 = r0 + 8;
            tile[r1 * RS2 + col]     = acc[mf][nf][2] + b.x;
            tile[r1 * RS2 + col + 1] = acc[mf][nf][3] + b.y;
        }
    }
    __syncthreads();

    // each warp: 8 rows of top-32
    #pragma unroll 1
    for (int r8 = 0; r8 < 8; r8++) {
        const int lrow = wid * 8 + r8;
        const int grow = row0 + lrow;
        if (grow >= n) break;             // warp-uniform

        const float* srcr = tile + lrow * RS2;
        float v[8]; uint32_t u[8];
        #pragma unroll
        for (int i = 0; i < 8; i++) {
            v[i] = srcr[lane + i * 32];
            uint32_t s = __float_as_uint(v[i]);
            u[i] = (s & 0x80000000u) ? ~s : (s | 0x80000000u);
        }

        // radix select with early exit (count == 32 -> unique separation)
        uint32_t T = 0;
        #pragma unroll 1
        for (int bit = 31; bit >= 0; bit--) {
            uint32_t cand = T | (1u << bit);
            int c = 0;
            #pragma unroll
            for (int i = 0; i < 8; i++) c += (u[i] >= cand);
            c = __reduce_add_sync(0xffffffffu, c);
            if (c >= KSEL) { T = cand; if (c == KSEL) break; }
        }
        // v32 = approx value of the 32nd largest = min over selected
        float mn = __uint_as_float(0x7f800000);   // +inf
        #pragma unroll
        for (int i = 0; i < 8; i++)
            if (u[i] >= T) mn = fminf(mn, v[i]);
        #pragma unroll
        for (int off = 16; off; off >>= 1)
            mn = fminf(mn, __shfl_xor_sync(0xffffffffu, mn, off));
        const float v32 = mn;
        const float hi_thr = v32 + 2.f * ERRB;
        const float lo_thr = v32 - 2.f * ERRB;

        int cntS = 0, cntB = 0, bm = 0;
        #pragma unroll
        for (int i = 0; i < 8; i++) {
            bool sure = v[i] > hi_thr;
            bool bnd  = !sure && (v[i] >= lo_thr);
            cntS += sure; cntB += bnd;
            if (bnd) bm |= (1 << i);
        }
        cntS = __reduce_add_sync(0xffffffffu, cntS);
        int cntBw = __reduce_add_sync(0xffffffffu, cntB);
        const int need = KSEL - cntS;

        int picked = 0;
        float ex[8];
        const bool exact_path = (cntBw != need);
        if (exact_path) {
            // exact fp32 recompute for boundary elements (rare)
            const float* fr = feat + (size_t)grow * DIM;
            #pragma unroll 1
            for (int i = 0; i < 8; i++) {
                uint32_t bal = __ballot_sync(0xffffffffu, (bm >> i) & 1);
                while (bal) {
                    int owner = __ffs(bal) - 1; bal &= bal - 1;
                    int col = owner + i * 32;
                    const float* wr = Wneigh + (size_t)col * DIM;
                    float p = 0.f;
                    #pragma unroll
                    for (int j = 0; j < 8; j++)
                        p = fmaf(fr[lane + j * 32], wr[lane + j * 32], p);
                    #pragma unroll
                    for (int off = 16; off; off >>= 1)
                        p += __shfl_xor_sync(0xffffffffu, p, off);
                    if (lane == owner) ex[i] = p + bneigh[col];
                }
            }
            int rem = need, avail = bm;
            while (rem > 0) {
                float bv = __uint_as_float(0xff800000);   // -inf
                int bc = 0x7fffffff;
                #pragma unroll
                for (int i = 0; i < 8; i++)
                    if ((avail >> i) & 1) {
                        float e = ex[i]; int c = lane + i * 32;
                        if (e > bv || (e == bv && c < bc)) { bv = e; bc = c; }
                    }
                #pragma unroll
                for (int off = 16; off; off >>= 1) {
                    float ov = __shfl_xor_sync(0xffffffffu, bv, off);
                    int   oc = __shfl_xor_sync(0xffffffffu, bc, off);
                    if (ov > bv || (ov == bv && oc < bc)) { bv = ov; bc = oc; }
                }
                if (lane == (bc & 31)) {
                    avail  &= ~(1 << (bc >> 5));
                    picked |=  (1 << (bc >> 5));
                }
                rem--;
            }
        } else {
            picked = bm;
        }

        // packed compaction write: val(24b rounded) | col(8b)
        const uint32_t ltmask = (1u << lane) - 1u;
        int basep = 0;
        uint32_t* __restrict__ dst = g_topk + (size_t)grow * KSEL;
        #pragma unroll
        for (int i = 0; i < 8; i++) {
            bool sure = v[i] > hi_thr;
            bool pick = (picked >> i) & 1;
            bool sel = sure || pick;
            float wv = (pick && exact_path) ? ex[i] : v[i];
            uint32_t bs = __ballot_sync(0xffffffffu, sel);
            if (sel) {
                int pos = basep + __popc(bs & ltmask);
                uint32_t bits = (__float_as_uint(wv) + 0x80u) & 0xFFFFFF00u;
                dst[pos] = bits | (uint32_t)(lane + i * 32);
            }
            basep += __popc(bs);
        }
    }
}

// ---------------------------------------------------------------------------
// Kernel 2: CSR SpMM (round-5 version; best so far).
// One warp per dst row; single smem accumulator, converged-warp RMW chain.
// ---------------------------------------------------------------------------
__global__ __launch_bounds__(256)
void spmm_kernel(const int* __restrict__ indices,
                 const int* __restrict__ indptr,
                 float* __restrict__ out, int n)
{
    __shared__ float accs[8][DIM];
    const int warp = threadIdx.x >> 5;
    const int lane = threadIdx.x & 31;
    const int row = blockIdx.x * 8 + warp;
    if (row >= n) return;

    volatile float* a = accs[warp];
    #pragma unroll
    for (int i = 0; i < 8; i++) a[lane + i * 32] = 0.f;
    __syncwarp();

    const int s = indptr[row];
    const int e = indptr[row + 1];
    int j = s;
    for (; j + 4 <= e; j += 4) {
        int i0 = indices[j], i1 = indices[j+1], i2 = indices[j+2], i3 = indices[j+3];
        uint32_t p0 = __ldg(&g_topk[(size_t)i0 * KSEL + lane]);
        uint32_t p1 = __ldg(&g_topk[(size_t)i1 * KSEL + lane]);
        uint32_t p2 = __ldg(&g_topk[(size_t)i2 * KSEL + lane]);
        uint32_t p3 = __ldg(&g_topk[(size_t)i3 * KSEL + lane]);
        a[p0 & 0xFF] += __uint_as_float(p0 & 0xFFFFFF00u);
        a[p1 & 0xFF] += __uint_as_float(p1 & 0xFFFFFF00u);
        a[p2 & 0xFF] += __uint_as_float(p2 & 0xFFFFFF00u);
        a[p3 & 0xFF] += __uint_as_float(p3 & 0xFFFFFF00u);
    }
    for (; j < e; j++) {
        uint32_t p0 = __ldg(&g_topk[(size_t)indices[j] * KSEL + lane]);
        a[p0 & 0xFF] += __uint_as_float(p0 & 0xFFFFFF00u);
    }
    __syncwarp();

    #pragma unroll
    for (int i = 0; i < 8; i++) {
        int c = lane + i * 32;
        out[(size_t)row * DIM + c] += a[c];
    }
}

// ---------------------------------------------------------------------------
extern "C" void kernel_launch(void* const* d_in, const int* in_sizes, int n_in,
                              void* d_out, int out_size)
{
    const float* feat    = (const float*)d_in[0];
    const float* Wself   = (const float*)d_in[1];
    const float* Wneigh  = (const float*)d_in[2];
    const float* bneigh  = (const float*)d_in[3];
    const int*   indices = (const int*)d_in[4];
    const int*   indptr  = (const int*)d_in[5];
    float* out = (float*)d_out;

    const int n = in_sizes[0] / DIM;   // 50000

    cudaFuncSetAttribute(gemm_topk_kernel,
                         cudaFuncAttributeMaxDynamicSharedMemorySize, GEMM_SMEM);

    // 0) fp32 -> fp16 conversion
    split_kernel<<<1024, 256>>>(feat, Wself, Wneigh, n);

    // 1) fused GEMM + top-k: h_self -> out, top-32(feat_neigh+b) -> g_topk
    dim3 ggrid(2, (n + 127) / 128);
    gemm_topk_kernel<<<ggrid, 512, GEMM_SMEM>>>(feat, Wneigh, bneigh, out, n);

    // 2) SpMM accumulate onto h_self
    int blocks_rows = (n + 7) / 8;
    spmm_kernel<<<blocks_rows, 256>>>(indices, indptr, out, n);
}